// round 14
// baseline (speedup 1.0000x reference)
#include <cuda_runtime.h>
#include <cstdint>
#include <cstddef>

#define DINLINE __device__ __forceinline__

static constexpr int MDIM = 4096;
static constexpr int NDIM = 4096;
static constexpr int KDIM = 4096;

static constexpr int BM = 128;
static constexpr int BN = 128;
static constexpr int BK = 128;                 // 128 s8 = one SW128 row
static constexpr int STAGES = 3;
static constexpr int A_TILE_BYTES = BM * BK;   // 16 KB
static constexpr int B_TILE_BYTES = BN * BK;   // 16 KB
static constexpr int STAGE_BYTES = A_TILE_BYTES + B_TILE_BYTES;  // 32 KB
static constexpr int SMEM_BYTES = STAGES * STAGE_BYTES;          // 96 KB -> 2 CTA/SM

// stream-K decomposition: tile = 128x128, unit = half the K range (16 iters)
static constexpr int TILES_X = NDIM / BN;           // 32
static constexpr int N_TILES = (MDIM / BM) * TILES_X;  // 1024
static constexpr int HALF_ITERS = 16;               // K iters per unit
static constexpr int TOTAL_UNITS = N_TILES * 2;     // 2048

// Scratch (allocation-free rule: __device__ globals)
__device__ __align__(16) int8_t g_a8[(size_t)MDIM * KDIM];    // mat1 as s8 [M,K]
__device__ __align__(16) int8_t g_b8t[(size_t)NDIM * KDIM];   // mat2^T as s8 [N,K]
__device__ __align__(16) int g_ws[(size_t)N_TILES * BM * BN]; // split-tile partials
__device__ int g_flag[N_TILES];                                // split-tile ready flags

// ---------------------------------------------------------------- PTX helpers
DINLINE uint32_t smem_u32(const void* p) {
    uint32_t a;
    asm("{ .reg .u64 t; cvta.to.shared.u64 t, %1; cvt.u32.u64 %0, t; }"
        : "=r"(a) : "l"(p));
    return a;
}

DINLINE uint32_t swz128(uint32_t off) { return off ^ ((off >> 3) & 0x70); }

DINLINE void cp16(uint32_t dst, const void* src) {
    asm volatile("cp.async.cg.shared.global [%0], [%1], 16;"
                 :: "r"(dst), "l"(src));
}

DINLINE void ldsm4(uint32_t* r, uint32_t addr) {
    asm volatile(
        "ldmatrix.sync.aligned.m8n8.x4.shared.b16 {%0, %1, %2, %3}, [%4];"
        : "=r"(r[0]), "=r"(r[1]), "=r"(r[2]), "=r"(r[3]) : "r"(addr));
}

DINLINE void mma_s8(int* d, const uint32_t* a, uint32_t b0, uint32_t b1) {
    asm volatile(
        "mma.sync.aligned.m16n8k32.row.col.s32.s8.s8.s32 "
        "{%0, %1, %2, %3}, {%4, %5, %6, %7}, {%8, %9}, {%0, %1, %2, %3};"
        : "+r"(d[0]), "+r"(d[1]), "+r"(d[2]), "+r"(d[3])
        : "r"(a[0]), "r"(a[1]), "r"(a[2]), "r"(a[3]), "r"(b0), "r"(b1));
}

// ---------------------------------------------------------------- flag reset
__global__ void reset_flags_kernel() {
    if (threadIdx.x < N_TILES) g_flag[threadIdx.x] = 0;
}

// ---------------------------------------------------------------- fused converter
static constexpr int CONV_A_BLOCKS  = (MDIM * KDIM / 4) / 256;      // 16384
static constexpr int CONV_BT_BLOCKS = (KDIM / 64) * (NDIM / 64);    // 4096

__global__ void __launch_bounds__(256)
conv_fused_kernel(const int* __restrict__ a, const int* __restrict__ b) {
    const int tid = threadIdx.x;
    if (blockIdx.x < CONV_A_BLOCKS) {
        size_t i = (size_t)blockIdx.x * 256 + tid;   // int4 index
        int4 v = reinterpret_cast<const int4*>(a)[i];
        uint32_t packed = (uint32_t)(v.x & 0xff)
                        | ((uint32_t)(v.y & 0xff) << 8)
                        | ((uint32_t)(v.z & 0xff) << 16)
                        | ((uint32_t)(v.w & 0xff) << 24);
        reinterpret_cast<uint32_t*>(g_a8)[i] = packed;
        return;
    }
    __shared__ int8_t tile[64][68];
    const int t64 = blockIdx.x - CONV_A_BLOCKS;
    const int n0 = (t64 & 63) * 64;
    const int k0 = (t64 >> 6) * 64;

    const int ln4 = (tid & 15) * 4;
    const int lk  = tid >> 4;
#pragma unroll
    for (int p = 0; p < 4; ++p) {
        const int k = lk + p * 16;
        int4 v = *reinterpret_cast<const int4*>(
            &b[(size_t)(k0 + k) * NDIM + n0 + ln4]);
        tile[ln4 + 0][k] = (int8_t)(v.x & 0xff);
        tile[ln4 + 1][k] = (int8_t)(v.y & 0xff);
        tile[ln4 + 2][k] = (int8_t)(v.z & 0xff);
        tile[ln4 + 3][k] = (int8_t)(v.w & 0xff);
    }
    __syncthreads();

    const int sn  = tid >> 4;
    const int sk4 = (tid & 15) * 4;
#pragma unroll
    for (int p = 0; p < 4; ++p) {
        const int n = sn + p * 16;
        uint32_t w = *reinterpret_cast<const uint32_t*>(&tile[n][sk4]);
        *reinterpret_cast<uint32_t*>(
            &g_b8t[(size_t)(n0 + n) * KDIM + k0 + sk4]) = w;
    }
}

// ---------------------------------------------------------------- stream-K GEMM
// Persistent grid (2 CTAs/SM). Work = 2048 half-K units; CTA c owns
// [c*2048/G, (c+1)*2048/G), processed in REVERSE so a CTA's range-end
// partial (producer) is emitted first and its range-start merge
// (consumer) happens last -> producers always finish long before
// consumers wait; dependency is c -> c-1 (launch order), deadlock-free.
__global__ void __launch_bounds__(128, 2)
gemm_sk_kernel(const int* __restrict__ inp, float* __restrict__ out, int G) {
    extern __shared__ uint8_t smem[];
    const uint32_t tiles = smem_u32(smem);

    const int tid = threadIdx.x;
    const int wid = tid >> 5;
    const int lane = tid & 31;
    const int wm = wid >> 1;      // 0..1 (64-row slices)
    const int wn = wid & 1;       // 0..1 (64-col slices)

    const int c = blockIdx.x;
    const int u_s = (int)((long long)c * TOTAL_UNITS / G);
    const int u_e = (int)((long long)(c + 1) * TOTAL_UNITS / G);

    // loader coords: 128 threads x 8 A-chunks + 8 B-chunks of 16B
    const int lrow = tid >> 3;             // 0..15 base row
    const int lko  = (tid & 7) << 4;       // byte offset in row
    const uint32_t lm_row = (uint32_t)(lane & 15);
    const uint32_t lm_ch  = (uint32_t)((lane >> 4) << 4);

    int u_hi = u_e;
#pragma unroll 1
    while (u_hi > u_s) {
        const int t = (u_hi - 1) >> 1;
        const int u_lo = (u_s > 2 * t) ? u_s : 2 * t;
        const int kit0 = (u_lo - 2 * t) * HALF_ITERS;   // 0 or 16
        const int kit1 = (u_hi - 2 * t) * HALF_ITERS;   // 16 or 32
        const int nk = kit1 - kit0;

        const int m0 = (t >> 5) * BM;
        const int n0 = (t & 31) * BN;
        const int8_t* __restrict__ gA =
            g_a8  + (size_t)(m0 + lrow) * KDIM + lko + (size_t)kit0 * BK;
        const int8_t* __restrict__ gB =
            g_b8t + (size_t)(n0 + lrow) * KDIM + lko + (size_t)kit0 * BK;

        int acc[4][8][4];
#pragma unroll
        for (int mi = 0; mi < 4; ++mi)
#pragma unroll
            for (int nb = 0; nb < 8; ++nb)
#pragma unroll
                for (int cc = 0; cc < 4; ++cc) acc[mi][nb][cc] = 0;

        // prologue: fill stages 0,1 (nk >= 16 > 2 always)
#pragma unroll
        for (int s = 0; s < STAGES - 1; ++s) {
            const uint32_t a_s = tiles + (uint32_t)s * STAGE_BYTES;
            const uint32_t b_s = a_s + A_TILE_BYTES;
#pragma unroll
            for (int tt = 0; tt < 8; ++tt) {
                int row = lrow + tt * 16;
                cp16(a_s + swz128((uint32_t)(row * BK + lko)),
                     gA + (size_t)tt * 16 * KDIM + s * BK);
                cp16(b_s + swz128((uint32_t)(row * BK + lko)),
                     gB + (size_t)tt * 16 * KDIM + s * BK);
            }
            asm volatile("cp.async.commit_group;" ::: "memory");
        }

        int ss = 0;      // compute stage
        int ss_st = 2;   // load stage
        int kb_ld = (STAGES - 1) * BK;

#pragma unroll 1
        for (int i = 0; i < nk; ++i) {
            asm volatile("cp.async.wait_group %0;" :: "n"(STAGES - 2) : "memory");
            __syncthreads();

            const uint32_t a_s = tiles + (uint32_t)ss * STAGE_BYTES;
            const uint32_t b_s = a_s + A_TILE_BYTES;

#pragma unroll
            for (int ks = 0; ks < 4; ++ks) {
                uint32_t afr[4][4], bfr[4][4];
#pragma unroll
                for (int mi = 0; mi < 4; ++mi) {
                    uint32_t row = (uint32_t)(wm * 64 + mi * 16) + lm_row;
                    ldsm4(afr[mi],
                          a_s + swz128(row * BK + (uint32_t)(ks * 32) + lm_ch));
                }
#pragma unroll
                for (int nf = 0; nf < 4; ++nf) {
                    uint32_t row = (uint32_t)(wn * 64 + nf * 16) + lm_row;
                    ldsm4(bfr[nf],
                          b_s + swz128(row * BK + (uint32_t)(ks * 32) + lm_ch));
                }
#pragma unroll
                for (int mi = 0; mi < 4; ++mi)
#pragma unroll
                    for (int nb = 0; nb < 8; ++nb)
                        mma_s8(acc[mi][nb], afr[mi], bfr[nb >> 1][nb & 1],
                               bfr[nb >> 1][(nb & 1) + 2]);
            }

            // issue next stage
            if (i + STAGES - 1 < nk) {
                const uint32_t an = tiles + (uint32_t)ss_st * STAGE_BYTES;
                const uint32_t bn = an + A_TILE_BYTES;
#pragma unroll
                for (int tt = 0; tt < 8; ++tt) {
                    int row = lrow + tt * 16;
                    cp16(an + swz128((uint32_t)(row * BK + lko)),
                         gA + (size_t)tt * 16 * KDIM + kb_ld);
                    cp16(bn + swz128((uint32_t)(row * BK + lko)),
                         gB + (size_t)tt * 16 * KDIM + kb_ld);
                }
            }
            asm volatile("cp.async.commit_group;" ::: "memory");

            ss    = (ss    == STAGES - 1) ? 0 : ss + 1;
            ss_st = (ss_st == STAGES - 1) ? 0 : ss_st + 1;
            kb_ld += BK;
        }
        asm volatile("cp.async.wait_all;" ::: "memory");

        if (kit1 == HALF_ITERS) {
            // -------- producer: first half only; stash partial, flag it
            int* ws = g_ws + (size_t)t * (BM * BN);
#pragma unroll
            for (int mi = 0; mi < 4; ++mi)
#pragma unroll
                for (int nb = 0; nb < 8; ++nb)
#pragma unroll
                    for (int cc = 0; cc < 4; ++cc) {
                        const int j = (mi * 8 + nb) * 4 + cc;
                        ws[j * 128 + tid] = acc[mi][nb][cc];
                    }
            __threadfence();
            __syncthreads();
            if (tid == 0) atomicExch(&g_flag[t], 1);
        } else {
            if (kit0 == HALF_ITERS) {
                // -------- consumer: merge producer's first-half partial
                if (tid == 0) while (atomicAdd(&g_flag[t], 0) == 0) {}
                __syncthreads();
                __threadfence();
                const int* ws = g_ws + (size_t)t * (BM * BN);
#pragma unroll
                for (int mi = 0; mi < 4; ++mi)
#pragma unroll
                    for (int nb = 0; nb < 8; ++nb)
#pragma unroll
                        for (int cc = 0; cc < 4; ++cc) {
                            const int j = (mi * 8 + nb) * 4 + cc;
                            acc[mi][nb][cc] += ws[j * 128 + tid];
                        }
            }
            // -------- epilogue: acc + input -> float
            const int rbase = m0 + wm * 64 + (lane >> 2);
            const int cbase = n0 + wn * 64 + ((lane & 3) << 1);
#pragma unroll
            for (int mi = 0; mi < 4; ++mi) {
#pragma unroll
                for (int nb = 0; nb < 8; ++nb) {
                    const int col = cbase + nb * 8;
                    const int r0 = rbase + mi * 16;
                    {
                        const size_t idx = (size_t)r0 * NDIM + col;
                        int2 iv = *reinterpret_cast<const int2*>(inp + idx);
                        float2 f;
                        f.x = (float)(acc[mi][nb][0] + iv.x);
                        f.y = (float)(acc[mi][nb][1] + iv.y);
                        *reinterpret_cast<float2*>(out + idx) = f;
                    }
                    {
                        const size_t idx = (size_t)(r0 + 8) * NDIM + col;
                        int2 iv = *reinterpret_cast<const int2*>(inp + idx);
                        float2 f;
                        f.x = (float)(acc[mi][nb][2] + iv.x);
                        f.y = (float)(acc[mi][nb][3] + iv.y);
                        *reinterpret_cast<float2*>(out + idx) = f;
                    }
                }
            }
        }
        __syncthreads();   // smem reuse safety before next segment
        u_hi = u_lo;
    }
}

// ---------------------------------------------------------------- launch
extern "C" void kernel_launch(void* const* d_in, const int* in_sizes, int n_in,
                              void* d_out, int out_size) {
    const int* inp = (const int*)d_in[0];   // input_tensor [M,N] int32
    const int* m1  = (const int*)d_in[1];   // mat1 [M,K] int32
    const int* m2  = (const int*)d_in[2];   // mat2 [K,N] int32
    float* out = (float*)d_out;

    int nsm = 0;
    cudaDeviceGetAttribute(&nsm, cudaDevAttrMultiProcessorCount, 0);
    const int G = (nsm > 0) ? 2 * nsm : 296;

    reset_flags_kernel<<<1, 1024>>>();
    conv_fused_kernel<<<CONV_A_BLOCKS + CONV_BT_BLOCKS, 256>>>(m1, m2);

    cudaFuncSetAttribute(gemm_sk_kernel,
                         cudaFuncAttributeMaxDynamicSharedMemorySize, SMEM_BYTES);
    gemm_sk_kernel<<<G, 128, SMEM_BYTES>>>(inp, out, G);
}